// round 13
// baseline (speedup 1.0000x reference)
#include <cuda_runtime.h>
#include <cuda_bf16.h>

// Problem constants (fixed by setup_inputs): B=8, D=1024, comp 24x24, orig 96x96,
// KERNEL=STRIDE=4, PAD=0 -> all window slots valid, non-overlapping tiling.
constexpr int B_   = 8;
constexpr int D_   = 1024;
constexpr int CH_  = 24, CW_ = 24;
constexpr int OH_  = 96, OW_ = 96;
constexpr int N_   = CH_ * CW_;       // 576 compressed tokens per batch
constexpr int ROWS_PB_ = OH_ * OW_;   // 9216 original rows per batch
constexpr int ITEMS_ = B_ * ROWS_PB_; // 73728 = one item per ORIGINAL row
constexpr float EPS_ = 1e-12f;

// Persistent launch: 888 CTAs x 8 warps = 7104 warps, 256 thr, occ 6 ->
// exactly 6 CTAs on every SM; items walked in original-row memory order
// (sequential chip-wide DRAM sweep). Each warp L2-prefetches its NEXT item's
// r row (1 line/lane = whole 4KB row in one instruction) one item ahead, so
// demand LDGs hit L2 (~240 cyc) instead of DRAM (~600+ cyc).
constexpr int CTAS_  = 888;
constexpr int WPB_   = 8;
constexpr int TOTW_  = CTAS_ * WPB_;   // 7104

constexpr int NBUCK_ = 32;

// Spread accumulator buckets (256B stride) + completion counter. Zero-init at
// module load; the finishing warp resets them so each graph replay starts clean.
__device__ float        g_buck[NBUCK_ * 64];   // bucket i at g_buck[i*64]
__device__ unsigned int g_count;

__global__ __launch_bounds__(256, 6)
void rf_sim_kernel(const float* __restrict__ comp, const float* __restrict__ orig,
                   float* __restrict__ out) {
    const int tid  = threadIdx.x;
    const int lane = tid & 31;
    const int wid  = tid >> 5;
    const int gw   = blockIdx.x * WPB_ + wid;   // global warp id

    float sim_acc = 0.f;

    // Prefetch the FIRST item's r row before entering the loop.
    if (gw < ITEMS_) {
        const float* rp = orig + (size_t)gw * D_ + lane * 32;  // 128B per lane
        asm volatile("prefetch.global.L2 [%0];" :: "l"(rp));
    }

    #pragma unroll 1
    for (int item = gw; item < ITEMS_; item += TOTW_) {
        // Prefetch next item's r row (~9k-cycle lookahead at this occupancy).
        const int nitem = item + TOTW_;
        if (nitem < ITEMS_) {
            const float* rp = orig + (size_t)nitem * D_ + lane * 32;
            asm volatile("prefetch.global.L2 [%0];" :: "l"(rp));
        }

        const int b     = item / ROWS_PB_;
        const int rowin = item - b * ROWS_PB_;
        const int oh    = rowin / OW_;
        const int ow    = rowin - oh * OW_;
        const int token = b * N_ + (oh >> 2) * CW_ + (ow >> 2);

        const float4* r4 = reinterpret_cast<const float4*>(orig) + (size_t)item * (D_ / 4);
        const float4* c4 = reinterpret_cast<const float4*>(comp) + (size_t)token * (D_ / 4);

        float dot = 0.f, rr = 0.f, cc = 0.f;
        // Two half-D batches of 4 r + 4 c float4 loads: 32 live data regs,
        // fits the 42-reg budget (occ 6) without spills. r is stream-once ->
        // evict-first (__ldcs), protecting comp's L2 residency (18.9MB < L2).
        #pragma unroll
        for (int h = 0; h < 2; h++) {
            const int base = h * 128 + lane;
            float4 r0 = __ldcs(&r4[base]);
            float4 r1 = __ldcs(&r4[base + 32]);
            float4 r2 = __ldcs(&r4[base + 64]);
            float4 r3 = __ldcs(&r4[base + 96]);
            float4 c0 = c4[base];
            float4 c1 = c4[base + 32];
            float4 c2 = c4[base + 64];
            float4 c3 = c4[base + 96];
            dot += r0.x*c0.x + r0.y*c0.y + r0.z*c0.z + r0.w*c0.w;
            rr  += r0.x*r0.x + r0.y*r0.y + r0.z*r0.z + r0.w*r0.w;
            cc  += c0.x*c0.x + c0.y*c0.y + c0.z*c0.z + c0.w*c0.w;
            dot += r1.x*c1.x + r1.y*c1.y + r1.z*c1.z + r1.w*c1.w;
            rr  += r1.x*r1.x + r1.y*r1.y + r1.z*r1.z + r1.w*r1.w;
            cc  += c1.x*c1.x + c1.y*c1.y + c1.z*c1.z + c1.w*c1.w;
            dot += r2.x*c2.x + r2.y*c2.y + r2.z*c2.z + r2.w*c2.w;
            rr  += r2.x*r2.x + r2.y*r2.y + r2.z*r2.z + r2.w*r2.w;
            cc  += c2.x*c2.x + c2.y*c2.y + c2.z*c2.z + c2.w*c2.w;
            dot += r3.x*c3.x + r3.y*c3.y + r3.z*c3.z + r3.w*c3.w;
            rr  += r3.x*r3.x + r3.y*r3.y + r3.z*r3.z + r3.w*r3.w;
            cc  += c3.x*c3.x + c3.y*c3.y + c3.z*c3.z + c3.w*c3.w;
        }
        #pragma unroll
        for (int o = 16; o > 0; o >>= 1) {
            dot += __shfl_xor_sync(0xffffffffu, dot, o);
            rr  += __shfl_xor_sync(0xffffffffu, rr,  o);
            cc  += __shfl_xor_sync(0xffffffffu, cc,  o);
        }
        // rsqrt: shorter dependent tail than sqrt+div; norms are O(30), far
        // from the eps edge.
        sim_acc += dot * rsqrtf(fmaxf(cc, EPS_ * EPS_)) * rsqrtf(fmaxf(rr, EPS_ * EPS_));
    }

    // One atomic per warp into a spread bucket; last warp to finish writes out.
    if (lane == 0) {
        atomicAdd(&g_buck[(gw & (NBUCK_ - 1)) * 64], sim_acc);
        __threadfence();
        unsigned prev = atomicAdd(&g_count, 1u);
        if (prev == (unsigned)(TOTW_ - 1)) {
            __threadfence();
            float tot = 0.f;
            #pragma unroll
            for (int i = 0; i < NBUCK_; i++)
                tot += *((volatile float*)&g_buck[i * 64]);
            out[0] = 1.0f - tot / (float)ITEMS_;
            // Reset for the next graph replay.
            #pragma unroll
            for (int i = 0; i < NBUCK_; i++)
                g_buck[i * 64] = 0.f;
            __threadfence();
            g_count = 0u;
        }
    }
}

extern "C" void kernel_launch(void* const* d_in, const int* in_sizes, int n_in,
                              void* d_out, int out_size) {
    const float* comp = (const float*)d_in[0];
    const float* orig = (const float*)d_in[1];
    rf_sim_kernel<<<CTAS_, 256>>>(comp, orig, (float*)d_out);
}

// round 14
// speedup vs baseline: 1.0788x; 1.0788x over previous
#include <cuda_runtime.h>
#include <cuda_bf16.h>

// Problem constants (fixed by setup_inputs): B=8, D=1024, comp 24x24, orig 96x96,
// KERNEL=STRIDE=4, PAD=0 -> all window slots valid, non-overlapping tiling.
constexpr int B_   = 8;
constexpr int D_   = 1024;
constexpr int CH_  = 24, CW_ = 24;
constexpr int OH_  = 96, OW_ = 96;
constexpr int N_   = CH_ * CW_;       // 576 compressed tokens per batch
constexpr int ROWS_PB_ = OH_ * OW_;   // 9216 original rows per batch
constexpr int ITEMS_ = B_ * ROWS_PB_; // 73728 = one item per ORIGINAL row
constexpr float EPS_ = 1e-12f;

// Persistent launch: 888 CTAs x 8 warps, 256 thr, occ 6 -> exactly 6 CTAs/SM.
// Row-linear order: a CTA's 8 warps process 8 CONSECUTIVE rows per iteration,
// which span exactly 2 compressed tokens (base = 0 mod 8, 8 | 96). The two c
// rows are staged in SMEM (double-buffered, one sync/iter), cutting c's
// global-load count 4x and freeing registers so each warp front-batches all
// 8 r float4 loads (full-item MLP) within the 42-reg occ-6 budget.
constexpr int CTAS_  = 888;
constexpr int WPB_   = 8;
constexpr int TOTW_  = CTAS_ * WPB_;   // 7104 items per chip-wide sweep step

constexpr int NBUCK_ = 32;

// Spread accumulator buckets (256B stride) + completion counter. Zero-init at
// module load; the finishing warp resets them so each graph replay starts clean.
__device__ float        g_buck[NBUCK_ * 64];   // bucket i at g_buck[i*64]
__device__ unsigned int g_count;

__global__ __launch_bounds__(256, 6)
void rf_sim_kernel(const float* __restrict__ comp, const float* __restrict__ orig,
                   float* __restrict__ out) {
    // [buffer][token 0/1][256 float4] = 16 KB; 6 CTAs/SM -> 96 KB < 228 KB.
    __shared__ float4 sc[2][2][D_ / 4 / 1];

    const int tid  = threadIdx.x;
    const int lane = tid & 31;
    const int wid  = tid >> 5;
    const int gw   = blockIdx.x * WPB_ + wid;   // global warp id (bucket pick)

    const float4* comp4 = reinterpret_cast<const float4*>(comp);

    // Token pair for a group starting at row `base` (base mod 8 == 0).
    auto tok0 = [&](int base) {
        const int b     = base / ROWS_PB_;
        const int rowin = base - b * ROWS_PB_;
        const int oh    = rowin / OW_;
        const int ow    = rowin - oh * OW_;
        return b * N_ + (oh >> 2) * CW_ + (ow >> 2);
    };

    // Preload group 0's two c rows into buffer 0 (thread tid copies one float4
    // of each row; 256 float4 == one full 4KB row).
    int base0 = blockIdx.x * WPB_;
    {
        const int t0 = tok0(base0);
        sc[0][0][tid] = comp4[(size_t)t0 * (D_ / 4) + tid];
        sc[0][1][tid] = comp4[(size_t)(t0 + 1) * (D_ / 4) + tid];
    }

    float sim_acc = 0.f;
    int buf = 0;

    #pragma unroll 1
    for (int base = base0; base < ITEMS_; base += TOTW_, buf ^= 1) {
        __syncthreads();   // buffer `buf` ready; prior reads of buf^1 complete

        // Prefetch NEXT group's c rows into the other buffer (overlaps compute).
        const int nbase = base + TOTW_;
        if (nbase < ITEMS_) {
            const int t0 = tok0(nbase);
            sc[buf ^ 1][0][tid] = comp4[(size_t)t0 * (D_ / 4) + tid];
            sc[buf ^ 1][1][tid] = comp4[(size_t)(t0 + 1) * (D_ / 4) + tid];
        }

        // My item: row base+wid; c row is token half (wid<4 -> 0, else 1).
        const int item = base + wid;
        const float4* r4 = reinterpret_cast<const float4*>(orig) + (size_t)item * (D_ / 4);
        const float4* c4 = sc[buf][wid >> 2];

        // Front-batch ALL 8 r loads (32 data regs) -> full-item MLP exposed.
        // r is stream-once -> evict-first (__ldcs).
        float4 r0 = __ldcs(&r4[lane]);
        float4 r1 = __ldcs(&r4[lane + 32]);
        float4 r2 = __ldcs(&r4[lane + 64]);
        float4 r3 = __ldcs(&r4[lane + 96]);
        float4 r4v = __ldcs(&r4[lane + 128]);
        float4 r5 = __ldcs(&r4[lane + 160]);
        float4 r6 = __ldcs(&r4[lane + 192]);
        float4 r7 = __ldcs(&r4[lane + 224]);

        float dot = 0.f, rr = 0.f, cc = 0.f;
        #pragma unroll
        for (int i = 0; i < 8; i++) {
            float4 r;
            switch (i) {
                case 0: r = r0; break; case 1: r = r1; break;
                case 2: r = r2; break; case 3: r = r3; break;
                case 4: r = r4v; break; case 5: r = r5; break;
                case 6: r = r6; break; default: r = r7; break;
            }
            const float4 c = c4[lane + i * 32];   // LDS.128, conflict-free
            dot += r.x * c.x + r.y * c.y + r.z * c.z + r.w * c.w;
            rr  += r.x * r.x + r.y * r.y + r.z * r.z + r.w * r.w;
            cc  += c.x * c.x + c.y * c.y + c.z * c.z + c.w * c.w;
        }
        #pragma unroll
        for (int o = 16; o > 0; o >>= 1) {
            dot += __shfl_xor_sync(0xffffffffu, dot, o);
            rr  += __shfl_xor_sync(0xffffffffu, rr,  o);
            cc  += __shfl_xor_sync(0xffffffffu, cc,  o);
        }
        // rsqrt: shorter dependent tail than sqrt+div; norms are O(30), far
        // from the eps edge.
        sim_acc += dot * rsqrtf(fmaxf(cc, EPS_ * EPS_)) * rsqrtf(fmaxf(rr, EPS_ * EPS_));
    }

    // One atomic per warp into a spread bucket; last warp to finish writes out.
    if (lane == 0) {
        atomicAdd(&g_buck[(gw & (NBUCK_ - 1)) * 64], sim_acc);
        __threadfence();
        unsigned prev = atomicAdd(&g_count, 1u);
        if (prev == (unsigned)(TOTW_ - 1)) {
            __threadfence();
            float tot = 0.f;
            #pragma unroll
            for (int i = 0; i < NBUCK_; i++)
                tot += *((volatile float*)&g_buck[i * 64]);
            out[0] = 1.0f - tot / (float)ITEMS_;
            // Reset for the next graph replay.
            #pragma unroll
            for (int i = 0; i < NBUCK_; i++)
                g_buck[i * 64] = 0.f;
            __threadfence();
            g_count = 0u;
        }
    }
}

extern "C" void kernel_launch(void* const* d_in, const int* in_sizes, int n_in,
                              void* d_out, int out_size) {
    const float* comp = (const float*)d_in[0];
    const float* orig = (const float*)d_in[1];
    rf_sim_kernel<<<CTAS_, 256>>>(comp, orig, (float*)d_out);
}

// round 15
// speedup vs baseline: 1.0902x; 1.0106x over previous
#include <cuda_runtime.h>
#include <cuda_bf16.h>

// Problem constants (fixed by setup_inputs): B=8, D=1024, comp 24x24, orig 96x96,
// KERNEL=STRIDE=4, PAD=0 -> all window slots valid, non-overlapping tiling.
constexpr int B_   = 8;
constexpr int D_   = 1024;
constexpr int CH_  = 24, CW_ = 24;
constexpr int OH_  = 96, OW_ = 96;
constexpr int N_   = CH_ * CW_;       // 576 compressed tokens per batch
constexpr int NT_  = B_ * N_;         // 4608 tokens
constexpr int KER_ = 4;
constexpr int WIN_ = KER_ * KER_;     // 16 window slots
constexpr int ITEMS_ = NT_ * WIN_;    // 73728 (token, slot) work items
constexpr float EPS_ = 1e-12f;

// Persistent launch: 768 CTAs x 8 warps = 6144 warps; 73728/6144 = exactly 12
// items per warp (zero tail imbalance). At occ 6 (42-reg cap) capacity is
// 148*6 = 888 CTAs -> single wave.
constexpr int CTAS_  = 768;
constexpr int WPB_   = 8;
constexpr int TOTW_  = CTAS_ * WPB_;  // 6144
constexpr int IPW_   = ITEMS_ / TOTW_; // 12

constexpr int NBUCK_ = 64;

// Spread accumulator buckets (256B stride: distinct L2 lines) + completion
// counter (counts warp arrivals). Zero-initialized at module load; the
// finishing warp resets everything so each graph replay starts clean.
__device__ float        g_buck[NBUCK_ * 64];   // bucket i at g_buck[i*64]
__device__ unsigned int g_count;

__global__ __launch_bounds__(256, 6)
void rf_sim_kernel(const float* __restrict__ comp, const float* __restrict__ orig,
                   float* __restrict__ out) {
    const int tid  = threadIdx.x;
    const int lane = tid & 31;
    const int wid  = tid >> 5;
    const int gw   = blockIdx.x * WPB_ + wid;   // global warp id

    float sim_acc = 0.f;

    // Persistent warps: each warp streams exactly IPW_ (token, slot) items so
    // loads stay continuously in flight (no CTA churn, no barriers).
    int item = gw;
    #pragma unroll 1
    for (int it = 0; it < IPW_; it++, item += TOTW_) {
        const int token = item >> 4;
        const int slot  = item & 15;
        const int b  = token / N_;
        const int t  = token - b * N_;
        const int Hc = t / CW_;
        const int Wc = t - Hc * CW_;
        const int dh = slot >> 2;
        const int dw = slot & 3;
        const int row = (Hc * KER_ + dh) * OW_ + (Wc * KER_ + dw);

        const float4* r4 = reinterpret_cast<const float4*>(
            orig + ((size_t)b * (OH_ * OW_) + row) * D_);
        const float4* c4 = reinterpret_cast<const float4*>(
            comp + (size_t)token * D_);

        float dot = 0.f, rr = 0.f, cc = 0.f;
        // Two half-D batches of 4 r + 4 c float4 loads: 32 live data regs,
        // fits the 42-reg budget (occ 6) without spills. r is stream-once ->
        // evict-first (__ldcs); c is reused 16x (L2-resident) -> default.
        #pragma unroll
        for (int h = 0; h < 2; h++) {
            const int base = h * 128 + lane;
            float4 r0 = __ldcs(&r4[base]);
            float4 r1 = __ldcs(&r4[base + 32]);
            float4 r2 = __ldcs(&r4[base + 64]);
            float4 r3 = __ldcs(&r4[base + 96]);
            float4 c0 = c4[base];
            float4 c1 = c4[base + 32];
            float4 c2 = c4[base + 64];
            float4 c3 = c4[base + 96];
            dot += r0.x*c0.x + r0.y*c0.y + r0.z*c0.z + r0.w*c0.w;
            rr  += r0.x*r0.x + r0.y*r0.y + r0.z*r0.z + r0.w*r0.w;
            cc  += c0.x*c0.x + c0.y*c0.y + c0.z*c0.z + c0.w*c0.w;
            dot += r1.x*c1.x + r1.y*c1.y + r1.z*c1.z + r1.w*c1.w;
            rr  += r1.x*r1.x + r1.y*r1.y + r1.z*r1.z + r1.w*r1.w;
            cc  += c1.x*c1.x + c1.y*c1.y + c1.z*c1.z + c1.w*c1.w;
            dot += r2.x*c2.x + r2.y*c2.y + r2.z*c2.z + r2.w*c2.w;
            rr  += r2.x*r2.x + r2.y*r2.y + r2.z*r2.z + r2.w*r2.w;
            cc  += c2.x*c2.x + c2.y*c2.y + c2.z*c2.z + c2.w*c2.w;
            dot += r3.x*c3.x + r3.y*c3.y + r3.z*c3.z + r3.w*c3.w;
            rr  += r3.x*r3.x + r3.y*r3.y + r3.z*r3.z + r3.w*r3.w;
            cc  += c3.x*c3.x + c3.y*c3.y + c3.z*c3.z + c3.w*c3.w;
        }
        #pragma unroll
        for (int o = 16; o > 0; o >>= 1) {
            dot += __shfl_xor_sync(0xffffffffu, dot, o);
            rr  += __shfl_xor_sync(0xffffffffu, rr,  o);
            cc  += __shfl_xor_sync(0xffffffffu, cc,  o);
        }
        sim_acc += dot / (fmaxf(sqrtf(cc), EPS_) * fmaxf(sqrtf(rr), EPS_));
    }

    // One atomic per warp into a spread bucket; last warp to finish writes out.
    if (lane == 0) {
        atomicAdd(&g_buck[(gw & (NBUCK_ - 1)) * 64], sim_acc);
        __threadfence();
        unsigned prev = atomicAdd(&g_count, 1u);
        if (prev == (unsigned)(TOTW_ - 1)) {
            __threadfence();
            float tot = 0.f;
            #pragma unroll
            for (int i = 0; i < NBUCK_; i++)
                tot += *((volatile float*)&g_buck[i * 64]);
            out[0] = 1.0f - tot / (float)ITEMS_;
            // Reset for the next graph replay.
            #pragma unroll
            for (int i = 0; i < NBUCK_; i++)
                g_buck[i * 64] = 0.f;
            __threadfence();
            g_count = 0u;
        }
    }
}

extern "C" void kernel_launch(void* const* d_in, const int* in_sizes, int n_in,
                              void* d_out, int out_size) {
    const float* comp = (const float*)d_in[0];
    const float* orig = (const float*)d_in[1];
    rf_sim_kernel<<<CTAS_, 256>>>(comp, orig, (float*)d_out);
}